// round 8
// baseline (speedup 1.0000x reference)
#include <cuda_runtime.h>
#include <cuda_fp16.h>
#include <math.h>
#include <stdint.h>

// ---------------- problem sizes ----------------
#define BSZ   8
#define NSZ   128
#define TSZ   2048
#define FSZ   32
#define LAGS  5
#define HID   64
#define TT    4              // timesteps per block tile
#define NCHUNK 8             // j-chunks of 16
#define JC    16
#define NTHREADS 256

// ---------------- smem layout (in __half units) ----------------
#define SA 24
#define SB 24
#define WS 40
#define A5_LAG (128 * SA)              // 3072 halfs
#define ST 21504
#define ST_BYTES (ST * 2)              // 43008
#define OFF_BX 15360                   // within stage
#define OFF_W  (2 * ST)                // 43008 halfs
#define OFF_BIAS_BYTES ((OFF_W + 64 * WS) * 2)   // 91136
#define SMEM_BYTES (OFF_BIAS_BYTES + 256)        // 91392

#define GRPB (16 * SB * 2)             // bytes per 16-row B group

__device__ uint4 g_A_h[81920];   // pre-converted fp16 A: 8*5*128*128 halfs

__device__ __forceinline__ uint32_t packh2(float lo, float hi) {
    uint32_t r;
    asm("cvt.rn.f16x2.f32 %0, %1, %2;" : "=r"(r) : "f"(hi), "f"(lo));
    return r;
}

#define LDSM_X4(r0, r1, r2, r3, addr) \
    asm volatile("ldmatrix.sync.aligned.m8n8.x4.shared.b16 {%0,%1,%2,%3}, [%4];" \
        : "=r"(r0), "=r"(r1), "=r"(r2), "=r"(r3) : "r"(addr))

#define CP_ASYNC16(dst, src) \
    asm volatile("cp.async.ca.shared.global [%0], [%1], 16;" :: "r"(dst), "l"(src))

__device__ __forceinline__ void mma_f16(float* d, uint32_t a0, uint32_t a1,
                                        uint32_t a2, uint32_t a3,
                                        uint32_t b0, uint32_t b1) {
    asm volatile(
        "mma.sync.aligned.m16n8k16.row.col.f32.f16.f16.f32 "
        "{%0,%1,%2,%3}, {%4,%5,%6,%7}, {%8,%9}, {%0,%1,%2,%3};"
        : "+f"(d[0]), "+f"(d[1]), "+f"(d[2]), "+f"(d[3])
        : "r"(a0), "r"(a1), "r"(a2), "r"(a3), "r"(b0), "r"(b1));
}

// GELU with Abramowitz-Stegun 7.1.26 erf (max abs err 1.5e-7), branch-free.
__device__ __forceinline__ float gelu_fast(float v) {
    float z = fabsf(v) * 0.70710678118654752440f;
    float t = __fdividef(1.0f, fmaf(0.3275911f, z, 1.0f));
    float p = fmaf(t, 1.061405429f, -1.453152027f);
    p = fmaf(p, t, 1.421413741f);
    p = fmaf(p, t, -0.284496736f);
    p = fmaf(p, t, 0.254829592f);
    p = p * t;
    float e = __expf(-z * z);
    float erfa = fmaf(-p, e, 1.0f);
    float erfv = copysignf(erfa, v);
    float hv = 0.5f * v;
    return fmaf(hv, erfv, hv);
}

__device__ __forceinline__ uint32_t smem_u32(const void* p) {
    uint32_t a;
    asm("{ .reg .u64 t; cvta.to.shared.u64 t, %1; cvt.u32.u64 %0, t; }" : "=r"(a) : "l"(p));
    return a;
}

// ---------------- prepass: A fp32 -> fp16 ----------------
__global__ void pggcn_prep(const float* __restrict__ A) {
    int i = blockIdx.x * 256 + threadIdx.x;
    float2 v = ((const float2*)A)[i];
    ((__half2*)g_A_h)[i] = __floats2half2_rn(v.x, v.y);
}

// ---------------- main fused kernel ----------------
__global__ __launch_bounds__(NTHREADS, 2)
void pggcn_main(const float* __restrict__ x,     // [B,N,T,F]
                const float* __restrict__ W,     // [HID,F]
                const float* __restrict__ bias,  // [HID]
                float* __restrict__ out)         // [B,N,T,HID]
{
    extern __shared__ __half smh[];
    const uint32_t sbase = smem_u32(smh);

    const int tid = threadIdx.x;
    const int wid = tid >> 5;
    const int lid = tid & 31;
    const int lq  = lid >> 2;
    const int lr  = lid & 3;
    const int b   = blockIdx.y;
    const int t0  = blockIdx.x * TT;

    const int m_base = (wid & 3) * 32;   // 4m x 2n warp grid
    const int n_base = (wid >> 2) * 64;

    const int la_row = ((lid >> 3) & 1) * 8 + (lid & 7);
    const int la_k   = (lid >> 4) * 8;
    const int lb_row = ((lid >> 4) & 1) * 8 + (lid & 7);
    const int lb_k   = ((lid >> 3) & 1) * 8;

    // ---- one-time fills: W (fp16) and bias
    {
#pragma unroll
        for (int it = 0; it < 4; it++) {
            int idx = it * NTHREADS + tid;
            int h = idx >> 4, wq = idx & 15;
            uint32_t w = packh2(W[h * FSZ + 2 * wq], W[h * FSZ + 2 * wq + 1]);
            *(uint32_t*)(smh + OFF_W + h * WS + 2 * wq) = w;
        }
        if (tid < HID) ((float*)((char*)smh + OFF_BIAS_BYTES))[tid] = bias[tid];
    }

    float acc[2][8][4];
#pragma unroll
    for (int i = 0; i < 2; i++)
#pragma unroll
        for (int j = 0; j < 8; j++)
#pragma unroll
            for (int k = 0; k < 4; k++) acc[i][j][k] = 0.0f;

    const uint32_t aA = sbase + 2 * ((m_base + la_row) * SA + la_k);
    const uint32_t aB = sbase + 2 * (OFF_BX + (n_base + lb_row) * SB + lb_k);

    // fill roles
    const int cp_i  = tid >> 1;
    const int cp_hh = tid & 1;
    const __half* Ah = (const __half*)g_A_h;
    const int bn  = tid;
    const int btl = bn >> 5;
    const int bf  = bn & 31;
    const int bts = t0 - 4 + btl;
    const size_t RS = (size_t)TSZ * FSZ;
    const float* xbase = x + ((size_t)b * NSZ) * RS + (size_t)(bts < 0 ? 0 : bts) * FSZ + bf;

    float bpf[16];

    // ---- prologue: fill chunk 0 into stage 0
    {
#pragma unroll
        for (int lag = 0; lag < LAGS; lag++) {
            const __half* src = Ah + (((size_t)(b * LAGS + lag) * NSZ) + cp_i) * NSZ
                                   + cp_hh * 8;
            uint32_t dst = sbase + 2 * (lag * A5_LAG + cp_i * SA + cp_hh * 8);
            CP_ASYNC16(dst, src);
        }
        asm volatile("cp.async.commit_group;" ::: "memory");
        if (bts >= 0) {
#pragma unroll
            for (int p = 0; p < 16; p++) bpf[p] = xbase[(size_t)p * RS];
        } else {
#pragma unroll
            for (int p = 0; p < 16; p++) bpf[p] = 0.0f;
        }
        uint4* dst = (uint4*)(smh + OFF_BX + bn * SB);
        dst[0] = make_uint4(packh2(bpf[0], bpf[1]),  packh2(bpf[2], bpf[3]),
                            packh2(bpf[4], bpf[5]),  packh2(bpf[6], bpf[7]));
        dst[1] = make_uint4(packh2(bpf[8], bpf[9]),  packh2(bpf[10], bpf[11]),
                            packh2(bpf[12], bpf[13]), packh2(bpf[14], bpf[15]));
        asm volatile("cp.async.wait_group 0;" ::: "memory");
    }
    __syncthreads();

    // ---- pipelined main loop ----
    for (int jc = 0; jc < NCHUNK; jc++) {
        const int cur = jc & 1;
        const int nxt = cur ^ 1;

        if (jc + 1 < NCHUNK) {
            const int j1 = (jc + 1) * JC;
#pragma unroll
            for (int lag = 0; lag < LAGS; lag++) {
                const __half* src = Ah + (((size_t)(b * LAGS + lag) * NSZ) + cp_i) * NSZ
                                       + j1 + cp_hh * 8;
                uint32_t dst = sbase + nxt * ST_BYTES
                             + 2 * (lag * A5_LAG + cp_i * SA + cp_hh * 8);
                CP_ASYNC16(dst, src);
            }
            asm volatile("cp.async.commit_group;" ::: "memory");
            if (bts >= 0) {
                const float* xb = xbase + (size_t)j1 * RS;
#pragma unroll
                for (int p = 0; p < 16; p++) bpf[p] = xb[(size_t)p * RS];
            }
        }

        // compute chunk jc: lags DESCENDING with sliding B-group window.
        // lag = 4-li uses B 16-row groups 2*li .. 2*li+3 (abs off from aB).
        {
            const uint32_t stB = cur * ST_BYTES;
            const uint32_t bBase = aB + stB;
            uint32_t bb[4][4];
            LDSM_X4(bb[0][0], bb[0][1], bb[0][2], bb[0][3], bBase + 0 * GRPB);
            LDSM_X4(bb[1][0], bb[1][1], bb[1][2], bb[1][3], bBase + 1 * GRPB);
            LDSM_X4(bb[2][0], bb[2][1], bb[2][2], bb[2][3], bBase + 2 * GRPB);
            LDSM_X4(bb[3][0], bb[3][1], bb[3][2], bb[3][3], bBase + 3 * GRPB);
#pragma unroll
            for (int li = 0; li < LAGS; li++) {
                const int lag = 4 - li;
                const uint32_t aL = aA + stB + lag * (A5_LAG * 2);
                uint32_t a0[4], a1[4];
                LDSM_X4(a0[0], a0[1], a0[2], a0[3], aL);
                LDSM_X4(a1[0], a1[1], a1[2], a1[3], aL + 16 * SA * 2);
#pragma unroll
                for (int nf2 = 0; nf2 < 4; nf2++) {
                    mma_f16(acc[0][2 * nf2],     a0[0], a0[1], a0[2], a0[3],
                            bb[nf2][0], bb[nf2][1]);
                    mma_f16(acc[0][2 * nf2 + 1], a0[0], a0[1], a0[2], a0[3],
                            bb[nf2][2], bb[nf2][3]);
                    mma_f16(acc[1][2 * nf2],     a1[0], a1[1], a1[2], a1[3],
                            bb[nf2][0], bb[nf2][1]);
                    mma_f16(acc[1][2 * nf2 + 1], a1[0], a1[1], a1[2], a1[3],
                            bb[nf2][2], bb[nf2][3]);
                }
                if (li < LAGS - 1) {
                    // slide window: keep top 2 groups, load 2 new
#pragma unroll
                    for (int q = 0; q < 4; q++) { bb[0][q] = bb[2][q]; bb[1][q] = bb[3][q]; }
                    LDSM_X4(bb[2][0], bb[2][1], bb[2][2], bb[2][3],
                            bBase + (2 * li + 4) * GRPB);
                    LDSM_X4(bb[3][0], bb[3][1], bb[3][2], bb[3][3],
                            bBase + (2 * li + 5) * GRPB);
                }
            }
        }

        if (jc + 1 < NCHUNK) {
            uint4* dst = (uint4*)(smh + nxt * ST + OFF_BX + bn * SB);
            if (bts >= 0) {
                dst[0] = make_uint4(packh2(bpf[0], bpf[1]),  packh2(bpf[2], bpf[3]),
                                    packh2(bpf[4], bpf[5]),  packh2(bpf[6], bpf[7]));
                dst[1] = make_uint4(packh2(bpf[8], bpf[9]),  packh2(bpf[10], bpf[11]),
                                    packh2(bpf[12], bpf[13]), packh2(bpf[14], bpf[15]));
            } else {
                dst[0] = make_uint4(0u, 0u, 0u, 0u);
                dst[1] = make_uint4(0u, 0u, 0u, 0u);
            }
            asm volatile("cp.async.wait_group 0;" ::: "memory");
        }
        __syncthreads();
    }

    // ---- stage 2 + epilogue: entirely from registers (C-frag == A-frag identity)
    {
        const uint32_t wB = sbase + 2 * (OFF_W + lb_row * WS + lb_k);
        const float* bias_s = (const float*)((char*)smh + OFF_BIAS_BYTES);
        const int tbase = (wid >> 2) * 2;

#pragma unroll
        for (int tg = 0; tg < 2; tg++) {
            uint32_t af[2][2][4];   // [kg][mf][a0..a3]
#pragma unroll
            for (int kg = 0; kg < 2; kg++) {
                const int nfA = tg * 4 + kg * 2;
#pragma unroll
                for (int mf = 0; mf < 2; mf++) {
                    af[kg][mf][0] = packh2(acc[mf][nfA][0],     acc[mf][nfA][1]);
                    af[kg][mf][1] = packh2(acc[mf][nfA][2],     acc[mf][nfA][3]);
                    af[kg][mf][2] = packh2(acc[mf][nfA + 1][0], acc[mf][nfA + 1][1]);
                    af[kg][mf][3] = packh2(acc[mf][nfA + 1][2], acc[mf][nfA + 1][3]);
                }
            }

            float a2[2][8][4];
#pragma unroll
            for (int i = 0; i < 2; i++)
#pragma unroll
                for (int j = 0; j < 8; j++)
#pragma unroll
                    for (int k = 0; k < 4; k++) a2[i][j][k] = 0.0f;

#pragma unroll
            for (int kg = 0; kg < 2; kg++) {
#pragma unroll
                for (int hq = 0; hq < 4; hq++) {
                    uint32_t wv[4];
                    LDSM_X4(wv[0], wv[1], wv[2], wv[3],
                            wB + hq * 16 * (WS * 2) + kg * 32);
#pragma unroll
                    for (int mf = 0; mf < 2; mf++) {
                        mma_f16(a2[mf][2 * hq],
                                af[kg][mf][0], af[kg][mf][1], af[kg][mf][2], af[kg][mf][3],
                                wv[0], wv[1]);
                        mma_f16(a2[mf][2 * hq + 1],
                                af[kg][mf][0], af[kg][mf][1], af[kg][mf][2], af[kg][mf][3],
                                wv[2], wv[3]);
                    }
                }
            }

            float* outB = out + (((size_t)b * NSZ) * TSZ + (t0 + tbase + tg)) * HID;
#pragma unroll
            for (int mf = 0; mf < 2; mf++) {
#pragma unroll
                for (int ho = 0; ho < 8; ho++) {
                    int r = m_base + mf * 16 + lq;
                    int h = ho * 8 + 2 * lr;
                    float bx = bias_s[h], by = bias_s[h + 1];
                    float2 o0, o1;
                    o0.x = gelu_fast(a2[mf][ho][0] + bx);
                    o0.y = gelu_fast(a2[mf][ho][1] + by);
                    o1.x = gelu_fast(a2[mf][ho][2] + bx);
                    o1.y = gelu_fast(a2[mf][ho][3] + by);
                    *(float2*)(outB + (size_t)r * (TSZ * HID) + h)       = o0;
                    *(float2*)(outB + (size_t)(r + 8) * (TSZ * HID) + h) = o1;
                }
            }
        }
    }
}

extern "C" void kernel_launch(void* const* d_in, const int* in_sizes, int n_in,
                              void* d_out, int out_size)
{
    const float* x    = (const float*)d_in[0];   // [8,128,2048,32]
    const float* A    = (const float*)d_in[1];   // [8,5,128,128]
    const float* W    = (const float*)d_in[2];   // [64,32]
    const float* bias = (const float*)d_in[3];   // [64]
    float* out = (float*)d_out;                  // [8,128,2048,64]
    (void)in_sizes; (void)n_in; (void)out_size;

    cudaFuncSetAttribute(pggcn_main,
                         cudaFuncAttributeMaxDynamicSharedMemorySize, SMEM_BYTES);

    pggcn_prep<<<1280, 256>>>(A);
    dim3 grid(TSZ / TT, BSZ);   // (512, 8)
    pggcn_main<<<grid, NTHREADS, SMEM_BYTES>>>(x, W, bias, out);
}

// round 9
// speedup vs baseline: 1.0454x; 1.0454x over previous
#include <cuda_runtime.h>
#include <cuda_fp16.h>
#include <math.h>
#include <stdint.h>

// ---------------- problem sizes ----------------
#define BSZ   8
#define NSZ   128
#define TSZ   2048
#define FSZ   32
#define LAGS  5
#define HID   64
#define TT    4              // timesteps per block tile
#define NCHUNK 8             // j-chunks of 16
#define JC    16
#define NTHREADS 256

// ---------------- smem layout (in __half units) ----------------
// stage s: A5 [5][128][SA=24] (15360) + Bx [16 k][264 n-stride] (4224) = 19584
// W [64][WS=40] after stages; bias floats after W.
#define SA 24
#define SBT 264                         // B tile n-stride (halfs): 256 + 8 pad
#define WS 40
#define A5_LAG (128 * SA)               // 3072 halfs
#define OFF_BXH 15360                   // within stage (halfs)
#define ST_H  (OFF_BXH + 16 * SBT)      // 19584 halfs per stage
#define ST_BYTES (ST_H * 2)             // 39168
#define OFF_WH (2 * ST_H)               // 39168 halfs
#define OFF_BIAS_BYTES ((OFF_WH + 64 * WS) * 2)  // 83456
#define SMEM_BYTES (OFF_BIAS_BYTES + 256)        // 83712

__device__ uint4 g_A_h[81920];   // pre-converted fp16 A: 8*5*128*128 halfs

__device__ __forceinline__ uint32_t packh2(float lo, float hi) {
    uint32_t r;
    asm("cvt.rn.f16x2.f32 %0, %1, %2;" : "=r"(r) : "f"(hi), "f"(lo));
    return r;
}

#define LDSM_X4(r0, r1, r2, r3, addr) \
    asm volatile("ldmatrix.sync.aligned.m8n8.x4.shared.b16 {%0,%1,%2,%3}, [%4];" \
        : "=r"(r0), "=r"(r1), "=r"(r2), "=r"(r3) : "r"(addr))

#define LDSM_X4T(r0, r1, r2, r3, addr) \
    asm volatile("ldmatrix.sync.aligned.m8n8.x4.trans.shared.b16 {%0,%1,%2,%3}, [%4];" \
        : "=r"(r0), "=r"(r1), "=r"(r2), "=r"(r3) : "r"(addr))

#define CP_ASYNC16(dst, src) \
    asm volatile("cp.async.ca.shared.global [%0], [%1], 16;" :: "r"(dst), "l"(src))

__device__ __forceinline__ void mma_f16(float* d, uint32_t a0, uint32_t a1,
                                        uint32_t a2, uint32_t a3,
                                        uint32_t b0, uint32_t b1) {
    asm volatile(
        "mma.sync.aligned.m16n8k16.row.col.f32.f16.f16.f32 "
        "{%0,%1,%2,%3}, {%4,%5,%6,%7}, {%8,%9}, {%0,%1,%2,%3};"
        : "+f"(d[0]), "+f"(d[1]), "+f"(d[2]), "+f"(d[3])
        : "r"(a0), "r"(a1), "r"(a2), "r"(a3), "r"(b0), "r"(b1));
}

// GELU with Abramowitz-Stegun 7.1.26 erf (max abs err 1.5e-7), branch-free.
__device__ __forceinline__ float gelu_fast(float v) {
    float z = fabsf(v) * 0.70710678118654752440f;
    float t = __fdividef(1.0f, fmaf(0.3275911f, z, 1.0f));
    float p = fmaf(t, 1.061405429f, -1.453152027f);
    p = fmaf(p, t, 1.421413741f);
    p = fmaf(p, t, -0.284496736f);
    p = fmaf(p, t, 0.254829592f);
    p = p * t;
    float e = __expf(-z * z);
    float erfa = fmaf(-p, e, 1.0f);
    float erfv = copysignf(erfa, v);
    float hv = 0.5f * v;
    return fmaf(hv, erfv, hv);
}

__device__ __forceinline__ uint32_t smem_u32(const void* p) {
    uint32_t a;
    asm("{ .reg .u64 t; cvta.to.shared.u64 t, %1; cvt.u32.u64 %0, t; }" : "=r"(a) : "l"(p));
    return a;
}

// ---------------- prepass: A fp32 -> fp16 ----------------
__global__ void pggcn_prep(const float* __restrict__ A) {
    int i = blockIdx.x * 256 + threadIdx.x;
    float2 v = ((const float2*)A)[i];
    ((__half2*)g_A_h)[i] = __floats2half2_rn(v.x, v.y);
}

// ---------------- main fused kernel ----------------
__global__ __launch_bounds__(NTHREADS, 2)
void pggcn_main(const float* __restrict__ x,     // [B,N,T,F]
                const float* __restrict__ W,     // [HID,F]
                const float* __restrict__ bias,  // [HID]
                float* __restrict__ out)         // [B,N,T,HID]
{
    extern __shared__ __half smh[];
    const uint32_t sbase = smem_u32(smh);

    const int tid = threadIdx.x;
    const int wid = tid >> 5;
    const int lid = tid & 31;
    const int lq  = lid >> 2;
    const int lr  = lid & 3;
    const int b   = blockIdx.y;
    const int t0  = blockIdx.x * TT;

    const int m_base = (wid & 3) * 32;   // 4m x 2n warp grid
    const int n_base = (wid >> 2) * 64;

    // A (non-trans) lane addressing
    const int la_row = ((lid >> 3) & 1) * 8 + (lid & 7);
    const int la_k   = (lid >> 4) * 8;
    // W (non-trans, stage-2 B) lane addressing
    const int lb_row = ((lid >> 4) & 1) * 8 + (lid & 7);
    const int lb_k   = ((lid >> 3) & 1) * 8;
    // B (trans) lane addressing: lanes supply k-rows of [k][n] tile
    const int kkB  = ((lid >> 3) & 1) * 8 + (lid & 7);
    const int nOffB = (lid >> 4) * 8;

    // ---- one-time fills: W (fp16) and bias
    {
#pragma unroll
        for (int it = 0; it < 4; it++) {
            int idx = it * NTHREADS + tid;
            int h = idx >> 4, wq = idx & 15;
            uint32_t w = packh2(W[h * FSZ + 2 * wq], W[h * FSZ + 2 * wq + 1]);
            *(uint32_t*)(smh + OFF_WH + h * WS + 2 * wq) = w;
        }
        if (tid < HID) ((float*)((char*)smh + OFF_BIAS_BYTES))[tid] = bias[tid];
    }

    float acc[2][8][4];
#pragma unroll
    for (int i = 0; i < 2; i++)
#pragma unroll
        for (int j = 0; j < 8; j++)
#pragma unroll
            for (int k = 0; k < 4; k++) acc[i][j][k] = 0.0f;

    const uint32_t aA = sbase + 2 * ((m_base + la_row) * SA + la_k);
    const uint32_t bT = sbase + 2 * (OFF_BXH + kkB * SBT + n_base + nOffB);

    // fill roles
    const int cp_i  = tid >> 1;
    const int cp_hh = tid & 1;
    const __half* Ah = (const __half*)g_A_h;
    const int fz_q4 = tid & 63;                 // float4 slot within a B row
    const bool bzero = (t0 == 0) && (fz_q4 < 32);   // cols t<0 (first 128 floats)

    // B row source helper: row k of chunk j0 = x[b][j0+k][(t0-4)*32 ..]
#define BROW(j0c, k) (x + ((size_t)(b * NSZ + (j0c) + (k))) * (TSZ * FSZ) + (t0 - 4) * FSZ)

// load one guarded float4 (phase element e: fi = e*256+tid -> k=fi>>6)
#define BLD(v, j0c, e) do { \
    int _k = ((e) * 256 + tid) >> 6; \
    v = bzero ? make_float4(0.f, 0.f, 0.f, 0.f) \
              : *(const float4*)(BROW(j0c, _k) + fz_q4 * 4); \
} while (0)

// store one converted float4 to stage st
#define BST(v, st, e) do { \
    int _k = ((e) * 256 + tid) >> 6; \
    uint2 _w; _w.x = packh2(v.x, v.y); _w.y = packh2(v.z, v.w); \
    *(uint2*)(smh + (st) * ST_H + OFF_BXH + _k * SBT + fz_q4 * 4) = _w; \
} while (0)

#define LDPAIR(P, addr) do { \
    LDSM_X4T((P)[0], (P)[1], (P)[2], (P)[3], (addr)); \
    LDSM_X4T((P)[4], (P)[5], (P)[6], (P)[7], (addr) + 32); \
} while (0)

#define MMASTEP(PL, PH) do { \
    mma_f16(acc[0][0], a0[0], a0[1], a0[2], a0[3], (PL)[0], (PL)[1]); \
    mma_f16(acc[0][1], a0[0], a0[1], a0[2], a0[3], (PL)[2], (PL)[3]); \
    mma_f16(acc[0][2], a0[0], a0[1], a0[2], a0[3], (PL)[4], (PL)[5]); \
    mma_f16(acc[0][3], a0[0], a0[1], a0[2], a0[3], (PL)[6], (PL)[7]); \
    mma_f16(acc[0][4], a0[0], a0[1], a0[2], a0[3], (PH)[0], (PH)[1]); \
    mma_f16(acc[0][5], a0[0], a0[1], a0[2], a0[3], (PH)[2], (PH)[3]); \
    mma_f16(acc[0][6], a0[0], a0[1], a0[2], a0[3], (PH)[4], (PH)[5]); \
    mma_f16(acc[0][7], a0[0], a0[1], a0[2], a0[3], (PH)[6], (PH)[7]); \
    mma_f16(acc[1][0], a1[0], a1[1], a1[2], a1[3], (PL)[0], (PL)[1]); \
    mma_f16(acc[1][1], a1[0], a1[1], a1[2], a1[3], (PL)[2], (PL)[3]); \
    mma_f16(acc[1][2], a1[0], a1[1], a1[2], a1[3], (PL)[4], (PL)[5]); \
    mma_f16(acc[1][3], a1[0], a1[1], a1[2], a1[3], (PL)[6], (PL)[7]); \
    mma_f16(acc[1][4], a1[0], a1[1], a1[2], a1[3], (PH)[0], (PH)[1]); \
    mma_f16(acc[1][5], a1[0], a1[1], a1[2], a1[3], (PH)[2], (PH)[3]); \
    mma_f16(acc[1][6], a1[0], a1[1], a1[2], a1[3], (PH)[4], (PH)[5]); \
    mma_f16(acc[1][7], a1[0], a1[1], a1[2], a1[3], (PH)[6], (PH)[7]); \
} while (0)

    // ---- prologue: fill chunk 0 into stage 0
    {
#pragma unroll
        for (int lag = 0; lag < LAGS; lag++) {
            const __half* src = Ah + (((size_t)(b * LAGS + lag) * NSZ) + cp_i) * NSZ
                                   + cp_hh * 8;
            uint32_t dst = sbase + 2 * (lag * A5_LAG + cp_i * SA + cp_hh * 8);
            CP_ASYNC16(dst, src);
        }
        asm volatile("cp.async.commit_group;" ::: "memory");
        float4 v0, v1, v2, v3;
        BLD(v0, 0, 0); BLD(v1, 0, 1); BLD(v2, 0, 2); BLD(v3, 0, 3);
        BST(v0, 0, 0); BST(v1, 0, 1); BST(v2, 0, 2); BST(v3, 0, 3);
        asm volatile("cp.async.wait_group 0;" ::: "memory");
    }
    __syncthreads();

    // ---- pipelined main loop ----
    for (int jc = 0; jc < NCHUNK; jc++) {
        const int cur = jc & 1;
        const int nxt = cur ^ 1;
        const bool more = (jc + 1 < NCHUNK);
        const int j1 = (jc + 1) * JC;
        const uint32_t stB = cur * ST_BYTES;

        // next-chunk A via cp.async (fully async)
        if (more) {
#pragma unroll
            for (int lag = 0; lag < LAGS; lag++) {
                const __half* src = Ah + (((size_t)(b * LAGS + lag) * NSZ) + cp_i) * NSZ
                                       + j1 + cp_hh * 8;
                uint32_t dst = sbase + nxt * ST_BYTES
                             + 2 * (lag * A5_LAG + cp_i * SA + cp_hh * 8);
                CP_ASYNC16(dst, src);
            }
            asm volatile("cp.async.commit_group;" ::: "memory");
        }

        float4 xv0, xv1;
        if (more) { BLD(xv0, j1, 0); BLD(xv1, j1, 1); }   // phase-0 LDG issued early

        // ---- compute: explicit descending-lag sequence, MOV-free window.
        // lag l uses B cols (4-l)*32 .. +64 (relative); pairs alternate roles.
        uint32_t P0[8], P1[8], a0[4], a1[4];
        const uint32_t bQ = bT + stB;
        LDPAIR(P0, bQ + 0);            // rel cols 0..32   (lag4 low)
        LDPAIR(P1, bQ + 64);           // rel cols 32..64  (lag4 high)

        {   // lag 4
            const uint32_t aL = aA + stB + 4 * (A5_LAG * 2);
            LDSM_X4(a0[0], a0[1], a0[2], a0[3], aL);
            LDSM_X4(a1[0], a1[1], a1[2], a1[3], aL + 16 * SA * 2);
            MMASTEP(P0, P1);
        }
        LDPAIR(P0, bQ + 128);          // rel cols 64..96
        {   // lag 3 (low = P1, high = P0)
            const uint32_t aL = aA + stB + 3 * (A5_LAG * 2);
            LDSM_X4(a0[0], a0[1], a0[2], a0[3], aL);
            LDSM_X4(a1[0], a1[1], a1[2], a1[3], aL + 16 * SA * 2);
            MMASTEP(P1, P0);
        }
        if (more) {                     // store phase 0, load phase 1
            BST(xv0, nxt, 0); BST(xv1, nxt, 1);
            BLD(xv0, j1, 2); BLD(xv1, j1, 3);
        }
        LDPAIR(P1, bQ + 192);          // rel cols 96..128
        {   // lag 2
            const uint32_t aL = aA + stB + 2 * (A5_LAG * 2);
            LDSM_X4(a0[0], a0[1], a0[2], a0[3], aL);
            LDSM_X4(a1[0], a1[1], a1[2], a1[3], aL + 16 * SA * 2);
            MMASTEP(P0, P1);
        }
        LDPAIR(P0, bQ + 256);          // rel cols 128..160
        {   // lag 1
            const uint32_t aL = aA + stB + 1 * (A5_LAG * 2);
            LDSM_X4(a0[0], a0[1], a0[2], a0[3], aL);
            LDSM_X4(a1[0], a1[1], a1[2], a1[3], aL + 16 * SA * 2);
            MMASTEP(P1, P0);
        }
        if (more) { BST(xv0, nxt, 2); BST(xv1, nxt, 3); }
        LDPAIR(P1, bQ + 320);          // rel cols 160..192
        {   // lag 0
            const uint32_t aL = aA + stB;
            LDSM_X4(a0[0], a0[1], a0[2], a0[3], aL);
            LDSM_X4(a1[0], a1[1], a1[2], a1[3], aL + 16 * SA * 2);
            MMASTEP(P0, P1);
        }

        if (more) asm volatile("cp.async.wait_group 0;" ::: "memory");
        __syncthreads();
    }

    // ---- stage 2 + epilogue: entirely from registers (C-frag == A-frag identity)
    {
        const uint32_t wB = sbase + 2 * (OFF_WH + lb_row * WS + lb_k);
        const float* bias_s = (const float*)((char*)smh + OFF_BIAS_BYTES);
        const int tbase = (wid >> 2) * 2;

#pragma unroll
        for (int tg = 0; tg < 2; tg++) {
            uint32_t af[2][2][4];   // [kg][mf][a0..a3]
#pragma unroll
            for (int kg = 0; kg < 2; kg++) {
                const int nfA = tg * 4 + kg * 2;
#pragma unroll
                for (int mf = 0; mf < 2; mf++) {
                    af[kg][mf][0] = packh2(acc[mf][nfA][0],     acc[mf][nfA][1]);
                    af[kg][mf][1] = packh2(acc[mf][nfA][2],     acc[mf][nfA][3]);
                    af[kg][mf][2] = packh2(acc[mf][nfA + 1][0], acc[mf][nfA + 1][1]);
                    af[kg][mf][3] = packh2(acc[mf][nfA + 1][2], acc[mf][nfA + 1][3]);
                }
            }

            float a2[2][8][4];
#pragma unroll
            for (int i = 0; i < 2; i++)
#pragma unroll
                for (int j = 0; j < 8; j++)
#pragma unroll
                    for (int k = 0; k < 4; k++) a2[i][j][k] = 0.0f;

#pragma unroll
            for (int kg = 0; kg < 2; kg++) {
#pragma unroll
                for (int hq = 0; hq < 4; hq++) {
                    uint32_t wv[4];
                    LDSM_X4(wv[0], wv[1], wv[2], wv[3],
                            wB + hq * 16 * (WS * 2) + kg * 32);
#pragma unroll
                    for (int mf = 0; mf < 2; mf++) {
                        mma_f16(a2[mf][2 * hq],
                                af[kg][mf][0], af[kg][mf][1], af[kg][mf][2], af[kg][mf][3],
                                wv[0], wv[1]);
                        mma_f16(a2[mf][2 * hq + 1],
                                af[kg][mf][0], af[kg][mf][1], af[kg][mf][2], af[kg][mf][3],
                                wv[2], wv[3]);
                    }
                }
            }

            float* outB = out + (((size_t)b * NSZ) * TSZ + (t0 + tbase + tg)) * HID;
#pragma unroll
            for (int mf = 0; mf < 2; mf++) {
#pragma unroll
                for (int ho = 0; ho < 8; ho++) {
                    int r = m_base + mf * 16 + lq;
                    int h = ho * 8 + 2 * lr;
                    float bx = bias_s[h], by = bias_s[h + 1];
                    float2 o0, o1;
                    o0.x = gelu_fast(a2[mf][ho][0] + bx);
                    o0.y = gelu_fast(a2[mf][ho][1] + by);
                    o1.x = gelu_fast(a2[mf][ho][2] + bx);
                    o1.y = gelu_fast(a2[mf][ho][3] + by);
                    *(float2*)(outB + (size_t)r * (TSZ * HID) + h)       = o0;
                    *(float2*)(outB + (size_t)(r + 8) * (TSZ * HID) + h) = o1;
                }
            }
        }
    }
}

extern "C" void kernel_launch(void* const* d_in, const int* in_sizes, int n_in,
                              void* d_out, int out_size)
{
    const float* x    = (const float*)d_in[0];   // [8,128,2048,32]
    const float* A    = (const float*)d_in[1];   // [8,5,128,128]
    const float* W    = (const float*)d_in[2];   // [64,32]
    const float* bias = (const float*)d_in[3];   // [64]
    float* out = (float*)d_out;                  // [8,128,2048,64]
    (void)in_sizes; (void)n_in; (void)out_size;

    cudaFuncSetAttribute(pggcn_main,
                         cudaFuncAttributeMaxDynamicSharedMemorySize, SMEM_BYTES);

    pggcn_prep<<<1280, 256>>>(A);
    dim3 grid(TSZ / TT, BSZ);   // (512, 8)
    pggcn_main<<<grid, NTHREADS, SMEM_BYTES>>>(x, W, bias, out);
}